// round 5
// baseline (speedup 1.0000x reference)
#include <cuda_runtime.h>
#include <cstdint>

#define BATCH 2
#define NSEQ 2048
#define DMODEL 1024
#define NHEAD 16
#define DHEAD 64
#define ATT_SCALE 0.125f   // 1/sqrt(64)
#define NEG_BIG (-1e30f)

// TF32 GEMM tiling
#define PADM 136                       // 128 + 8: (8*tig + g) distinct mod 32 -> conflict-free
#define KSTEP 16
#define SBUF (KSTEP * PADM)            // uint2 per k-tile buffer   = 2176
#define SMAT (2 * SBUF)                // per matrix, double-buffered = 4352
#define GEMM_SMEM_BYTES (2 * SMAT * (int)sizeof(uint2))   // 69632

// Scratch (allocation-free: __device__ globals)
__device__ float g_q[(size_t)BATCH * NHEAD * NSEQ * DHEAD];   // [b,h,n,dh]
__device__ float g_k[(size_t)BATCH * NHEAD * NSEQ * DHEAD];
__device__ float g_v[(size_t)BATCH * NHEAD * NSEQ * DHEAD];
__device__ float g_y[(size_t)BATCH * NSEQ * DMODEL];          // [b,n,d]

// ---------------------------------------------------------------------------
// TF32 helpers
// ---------------------------------------------------------------------------
__device__ __forceinline__ unsigned f2tf(float x) {
    unsigned r;
    asm("cvt.rna.tf32.f32 %0, %1;" : "=r"(r) : "f"(x));
    return r;
}
// split x into (hi, lo) tf32 pair: x ~= hi + lo, |residual| ~ 2^-21 |x|
__device__ __forceinline__ uint2 split_tf32(float x) {
    unsigned hi = f2tf(x);
    float lof = x - __uint_as_float(hi);
    return make_uint2(hi, f2tf(lof));
}
__device__ __forceinline__ void mma8(float d[4], const unsigned a[4],
                                     unsigned b0, unsigned b1) {
    asm volatile(
        "mma.sync.aligned.m16n8k8.row.col.f32.tf32.tf32.f32 "
        "{%0,%1,%2,%3}, {%4,%5,%6,%7}, {%8,%9}, {%0,%1,%2,%3};"
        : "+f"(d[0]), "+f"(d[1]), "+f"(d[2]), "+f"(d[3])
        : "r"(a[0]), "r"(a[1]), "r"(a[2]), "r"(a[3]), "r"(b0), "r"(b1));
}

// ===========================================================================
// 3xTF32 NT sgemm core: C[m][c] = sum_k A[m][k] * B[c][k], K = DMODEL.
// 128x128 block, 256 threads (8 warps, 2x4 warp grid, 64x32 warp tile),
// k-step 16, double-buffered smem of (hi,lo) uint2 pairs.
// Fragment map (m16n8k8): a0=(g,tig) a1=(g+8,tig) a2=(g,tig+4) a3=(g+8,tig+4)
//                         b0=(k=tig,n=g) b1=(k=tig+4,n=g)
//                         c0=(g,2tig) c1=(g,2tig+1) c2,c3 = rows +8
// ===========================================================================
#define GEMM_TC_BODY(APTR, BPTR)                                               \
    extern __shared__ uint2 su[];                                              \
    uint2* As = su;                                                            \
    uint2* Bs = su + SMAT;                                                     \
    const int tid = threadIdx.x;                                               \
    const int lane = tid & 31, wid = tid >> 5;                                 \
    const int g = lane >> 2, tig = lane & 3;                                   \
    const int warpM = wid >> 2, warpN = wid & 3;                               \
    const int mBase = blockIdx.y << 7, cBase = blockIdx.x << 7;                \
    const int lrow = tid >> 1, lkc = (tid & 1) << 3;                           \
    const float* aptr = (APTR) + (size_t)(mBase + lrow) * DMODEL + lkc;        \
    const float* bptr = (BPTR) + (size_t)(cBase + lrow) * DMODEL + lkc;        \
    float acc[4][4][4] = {};                                                   \
    {   /* preload tile 0 into buffer 0 */                                     \
        float4 av0 = *(const float4*)(aptr);                                   \
        float4 av1 = *(const float4*)(aptr + 4);                               \
        float4 bv0 = *(const float4*)(bptr);                                   \
        float4 bv1 = *(const float4*)(bptr + 4);                               \
        float a8[8] = {av0.x, av0.y, av0.z, av0.w, av1.x, av1.y, av1.z, av1.w};\
        float b8[8] = {bv0.x, bv0.y, bv0.z, bv0.w, bv1.x, bv1.y, bv1.z, bv1.w};\
        _Pragma("unroll")                                                      \
        for (int j = 0; j < 8; j++) {                                          \
            As[(lkc + j) * PADM + lrow] = split_tf32(a8[j]);                   \
            Bs[(lkc + j) * PADM + lrow] = split_tf32(b8[j]);                   \
        }                                                                      \
    }                                                                          \
    __syncthreads();                                                           \
    int buf = 0;                                                               \
    for (int kt = 0; kt < DMODEL / KSTEP; kt++) {                              \
        float a8[8], b8[8];                                                    \
        const bool more = (kt + 1) < DMODEL / KSTEP;                           \
        if (more) {                                                            \
            const int off = (kt + 1) * KSTEP;                                  \
            float4 av0 = *(const float4*)(aptr + off);                         \
            float4 av1 = *(const float4*)(aptr + off + 4);                     \
            float4 bv0 = *(const float4*)(bptr + off);                         \
            float4 bv1 = *(const float4*)(bptr + off + 4);                     \
            a8[0]=av0.x; a8[1]=av0.y; a8[2]=av0.z; a8[3]=av0.w;                \
            a8[4]=av1.x; a8[5]=av1.y; a8[6]=av1.z; a8[7]=av1.w;                \
            b8[0]=bv0.x; b8[1]=bv0.y; b8[2]=bv0.z; b8[3]=bv0.w;                \
            b8[4]=bv1.x; b8[5]=bv1.y; b8[6]=bv1.z; b8[7]=bv1.w;                \
        }                                                                      \
        const int bofs = buf * SBUF;                                           \
        _Pragma("unroll")                                                      \
        for (int kc = 0; kc < KSTEP; kc += 8) {                                \
            unsigned ahi[4][4], alo[4][4], bhi[4][2], blo[4][2];               \
            const int kA = kc + tig;                                           \
            _Pragma("unroll")                                                  \
            for (int mf = 0; mf < 4; mf++) {                                   \
                const int r = (warpM << 6) + (mf << 4) + g;                    \
                uint2 p0 = As[bofs + kA * PADM + r];                           \
                uint2 p1 = As[bofs + kA * PADM + r + 8];                       \
                uint2 p2 = As[bofs + (kA + 4) * PADM + r];                     \
                uint2 p3 = As[bofs + (kA + 4) * PADM + r + 8];                 \
                ahi[mf][0] = p0.x; alo[mf][0] = p0.y;                          \
                ahi[mf][1] = p1.x; alo[mf][1] = p1.y;                          \
                ahi[mf][2] = p2.x; alo[mf][2] = p2.y;                          \
                ahi[mf][3] = p3.x; alo[mf][3] = p3.y;                          \
            }                                                                  \
            _Pragma("unroll")                                                  \
            for (int nf = 0; nf < 4; nf++) {                                   \
                const int n = (warpN << 5) + (nf << 3) + g;                    \
                uint2 q0 = Bs[bofs + kA * PADM + n];                           \
                uint2 q1 = Bs[bofs + (kA + 4) * PADM + n];                     \
                bhi[nf][0] = q0.x; blo[nf][0] = q0.y;                          \
                bhi[nf][1] = q1.x; blo[nf][1] = q1.y;                          \
            }                                                                  \
            _Pragma("unroll")                                                  \
            for (int mf = 0; mf < 4; mf++) {                                   \
                _Pragma("unroll")                                              \
                for (int nf = 0; nf < 4; nf++) {                               \
                    mma8(acc[mf][nf], ahi[mf], bhi[nf][0], bhi[nf][1]);        \
                    mma8(acc[mf][nf], alo[mf], bhi[nf][0], bhi[nf][1]);        \
                    mma8(acc[mf][nf], ahi[mf], blo[nf][0], blo[nf][1]);        \
                }                                                              \
            }                                                                  \
        }                                                                      \
        if (more) {                                                            \
            const int nofs = (buf ^ 1) * SBUF;                                 \
            _Pragma("unroll")                                                  \
            for (int j = 0; j < 8; j++) {                                      \
                As[nofs + (lkc + j) * PADM + lrow] = split_tf32(a8[j]);        \
                Bs[nofs + (lkc + j) * PADM + lrow] = split_tf32(b8[j]);        \
            }                                                                  \
            __syncthreads();                                                   \
            buf ^= 1;                                                          \
        }                                                                      \
    }

// ---------------------------------------------------------------------------
// Kernel 1: qkv = x @ Wqkv^T, scattered into g_q/g_k/g_v in [b,h,n,dh] layout.
// grid (3072/128, 4096/128) = (24, 32)
// ---------------------------------------------------------------------------
__global__ __launch_bounds__(256) void qkv_kernel(const float* __restrict__ x,
                                                  const float* __restrict__ W) {
    GEMM_TC_BODY(x, W)

#pragma unroll
    for (int mf = 0; mf < 4; mf++) {
#pragma unroll
        for (int nf = 0; nf < 4; nf++) {
            const int c = cBase + (warpN << 5) + (nf << 3) + (tig << 1);
            const int three = c >> 10;
            const int hh = (c >> 6) & (NHEAD - 1);
            const int dh0 = c & 63;
            float* dst = (three == 0) ? g_q : (three == 1) ? g_k : g_v;
            const int m0 = mBase + (warpM << 6) + (mf << 4) + g;
#pragma unroll
            for (int rr = 0; rr < 2; rr++) {
                const int m = m0 + rr * 8;
                const int b = m >> 11;
                const int n = m & (NSEQ - 1);
                const size_t idx = (((size_t)(b * NHEAD + hh) * NSEQ + n) << 6) + dh0;
                *(float2*)&dst[idx] =
                    make_float2(acc[mf][nf][rr * 2], acc[mf][nf][rr * 2 + 1]);
            }
        }
    }
}

// ---------------------------------------------------------------------------
// Kernel 3: out = y @ Wproj^T + bproj.   grid (1024/128, 4096/128) = (8, 32)
// ---------------------------------------------------------------------------
__global__ __launch_bounds__(256) void proj_kernel(const float* __restrict__ Wp,
                                                   const float* __restrict__ bproj,
                                                   float* __restrict__ out) {
    GEMM_TC_BODY(g_y, Wp)

#pragma unroll
    for (int mf = 0; mf < 4; mf++) {
#pragma unroll
        for (int nf = 0; nf < 4; nf++) {
            const int c = cBase + (warpN << 5) + (nf << 3) + (tig << 1);
            const float2 bb = *(const float2*)&bproj[c];
            const int m0 = mBase + (warpM << 6) + (mf << 4) + g;
#pragma unroll
            for (int rr = 0; rr < 2; rr++) {
                const int m = m0 + rr * 8;
                *(float2*)&out[(size_t)m * DMODEL + c] =
                    make_float2(acc[mf][nf][rr * 2] + bb.x,
                                acc[mf][nf][rr * 2 + 1] + bb.y);
            }
        }
    }
}

// ---------------------------------------------------------------------------
// Kernel 2: flash attention with bias + key-padding mask (unchanged, passing).
// grid.x = q-tile (N/64), grid.y = b*H + h. 256 threads.
// ---------------------------------------------------------------------------
__global__ __launch_bounds__(256) void attn_kernel(const float* __restrict__ attn_bias,
                                                   const unsigned int* __restrict__ mask) {
    extern __shared__ __align__(16) float sm[];
    float* qs  = sm;             // 4096
    float* kst = sm + 4096;      // 4096
    float* vs  = sm + 8192;      // 4096
    float* ps  = sm + 12288;     // 4096

    const int tid = threadIdx.x;
    const int tx = tid & 15, ty = tid >> 4;
    const int q0 = blockIdx.x << 6;
    const int bh = blockIdx.y;
    const int b = bh >> 4, h = bh & 15;

    const float* qg = g_q + (size_t)bh * NSEQ * DHEAD;
    const float* kg = g_k + (size_t)bh * NSEQ * DHEAD;
    const float* vg = g_v + (size_t)bh * NSEQ * DHEAD;
    const float* biasg = attn_bias + ((size_t)b * NSEQ + q0) * NSEQ;
    const unsigned int* maskg = mask + b * NSEQ;

#pragma unroll
    for (int t = 0; t < 4; t++) {
        int p = tid + t * 256;
        int r = p >> 4, ch = (p & 15) << 2;
        *(float4*)&qs[r * 64 + ch] = *(const float4*)&qg[(size_t)(q0 + r) * 64 + ch];
    }

    float m_i[4], l_i[4], o[4][4];
#pragma unroll
    for (int i = 0; i < 4; i++) {
        m_i[i] = NEG_BIG; l_i[i] = 0.0f;
        o[i][0] = o[i][1] = o[i][2] = o[i][3] = 0.0f;
    }
    const int r0 = ty << 2;
    const int c0 = tx << 2;
    const int jrow = tid >> 2;
    const int dc   = (tid & 3) << 2;

    for (int kt = 0; kt < NSEQ / 64; kt++) {
        const int kb = kt << 6;
        if (maskg[kb] == 0u) break;   // prefix mask

        float4 kv4[4], vv4[4];
#pragma unroll
        for (int u = 0; u < 4; u++) {
            kv4[u] = *(const float4*)&kg[(size_t)(kb + jrow) * 64 + dc + u * 16];
            vv4[u] = *(const float4*)&vg[(size_t)(kb + jrow) * 64 + dc + u * 16];
        }
        __syncthreads();
#pragma unroll
        for (int u = 0; u < 4; u++) {
            int dh = dc + u * 16;
            kst[(dh + 0) * 64 + jrow] = kv4[u].x;
            kst[(dh + 1) * 64 + jrow] = kv4[u].y;
            kst[(dh + 2) * 64 + jrow] = kv4[u].z;
            kst[(dh + 3) * 64 + jrow] = kv4[u].w;
            *(float4*)&vs[jrow * 64 + dh] = vv4[u];
        }
        __syncthreads();

        float s[4][4] = {};
#pragma unroll
        for (int dh = 0; dh < 64; dh += 4) {
            float4 qv[4];
#pragma unroll
            for (int i = 0; i < 4; i++) qv[i] = *(const float4*)&qs[(r0 + i) * 64 + dh];
#pragma unroll
            for (int w = 0; w < 4; w++) {
                float4 kk = *(const float4*)&kst[(dh + w) * 64 + c0];
#pragma unroll
                for (int i = 0; i < 4; i++) {
                    float qq = (w == 0) ? qv[i].x : (w == 1) ? qv[i].y : (w == 2) ? qv[i].z : qv[i].w;
                    s[i][0] += qq * kk.x; s[i][1] += qq * kk.y;
                    s[i][2] += qq * kk.z; s[i][3] += qq * kk.w;
                }
            }
        }

        uint4 mk = *(const uint4*)&maskg[kb + c0];
#pragma unroll
        for (int i = 0; i < 4; i++) {
            float4 bb = *(const float4*)&biasg[(size_t)(r0 + i) * NSEQ + kb + c0];
            s[i][0] = mk.x ? (s[i][0] * ATT_SCALE + bb.x) : NEG_BIG;
            s[i][1] = mk.y ? (s[i][1] * ATT_SCALE + bb.y) : NEG_BIG;
            s[i][2] = mk.z ? (s[i][2] * ATT_SCALE + bb.z) : NEG_BIG;
            s[i][3] = mk.w ? (s[i][3] * ATT_SCALE + bb.w) : NEG_BIG;
        }

#pragma unroll
        for (int i = 0; i < 4; i++) {
            float mx = fmaxf(fmaxf(s[i][0], s[i][1]), fmaxf(s[i][2], s[i][3]));
            mx = fmaxf(mx, __shfl_xor_sync(0xffffffffu, mx, 1));
            mx = fmaxf(mx, __shfl_xor_sync(0xffffffffu, mx, 2));
            mx = fmaxf(mx, __shfl_xor_sync(0xffffffffu, mx, 4));
            mx = fmaxf(mx, __shfl_xor_sync(0xffffffffu, mx, 8));
            float mnew = fmaxf(m_i[i], mx);
            float alpha = __expf(m_i[i] - mnew);
            float p0 = __expf(s[i][0] - mnew);
            float p1 = __expf(s[i][1] - mnew);
            float p2 = __expf(s[i][2] - mnew);
            float p3 = __expf(s[i][3] - mnew);
            float rs = p0 + p1 + p2 + p3;
            rs += __shfl_xor_sync(0xffffffffu, rs, 1);
            rs += __shfl_xor_sync(0xffffffffu, rs, 2);
            rs += __shfl_xor_sync(0xffffffffu, rs, 4);
            rs += __shfl_xor_sync(0xffffffffu, rs, 8);
            l_i[i] = l_i[i] * alpha + rs;
            m_i[i] = mnew;
            o[i][0] *= alpha; o[i][1] *= alpha; o[i][2] *= alpha; o[i][3] *= alpha;
            *(float4*)&ps[(r0 + i) * 64 + c0] = make_float4(p0, p1, p2, p3);
        }
        __syncthreads();

#pragma unroll
        for (int j = 0; j < 64; j += 4) {
            float4 pv[4];
#pragma unroll
            for (int i = 0; i < 4; i++) pv[i] = *(const float4*)&ps[(r0 + i) * 64 + j];
#pragma unroll
            for (int w = 0; w < 4; w++) {
                float4 vv = *(const float4*)&vs[(j + w) * 64 + c0];
#pragma unroll
                for (int i = 0; i < 4; i++) {
                    float pp = (w == 0) ? pv[i].x : (w == 1) ? pv[i].y : (w == 2) ? pv[i].z : pv[i].w;
                    o[i][0] += pp * vv.x; o[i][1] += pp * vv.y;
                    o[i][2] += pp * vv.z; o[i][3] += pp * vv.w;
                }
            }
        }
    }

#pragma unroll
    for (int i = 0; i < 4; i++) {
        float inv = 1.0f / l_i[i];
        float4 r = make_float4(o[i][0] * inv, o[i][1] * inv, o[i][2] * inv, o[i][3] * inv);
        *(float4*)&g_y[((size_t)(b * NSEQ) + q0 + r0 + i) * DMODEL + h * 64 + c0] = r;
    }
}

// ---------------------------------------------------------------------------
extern "C" void kernel_launch(void* const* d_in, const int* in_sizes, int n_in,
                              void* d_out, int out_size) {
    const float* x          = (const float*)d_in[0];
    const float* attn_bias  = (const float*)d_in[1];
    const unsigned int* msk = (const unsigned int*)d_in[2];
    const float* Wqkv       = (const float*)d_in[3];
    const float* Wproj      = (const float*)d_in[4];
    const float* bproj      = (const float*)d_in[5];
    float* out = (float*)d_out;

    (void)in_sizes; (void)n_in; (void)out_size;

    cudaFuncSetAttribute((const void*)qkv_kernel,
                         cudaFuncAttributeMaxDynamicSharedMemorySize, GEMM_SMEM_BYTES);
    cudaFuncSetAttribute((const void*)proj_kernel,
                         cudaFuncAttributeMaxDynamicSharedMemorySize, GEMM_SMEM_BYTES);
    cudaFuncSetAttribute((const void*)attn_kernel,
                         cudaFuncAttributeMaxDynamicSharedMemorySize, 65536);

    qkv_kernel<<<dim3(24, 32), 256, GEMM_SMEM_BYTES>>>(x, Wqkv);
    attn_kernel<<<dim3(NSEQ / 64, BATCH * NHEAD), 256, 65536>>>(attn_bias, msk);
    proj_kernel<<<dim3(8, 32), 256, GEMM_SMEM_BYTES>>>(Wproj, bproj, out);
}

// round 8
// speedup vs baseline: 1.0733x; 1.0733x over previous
#include <cuda_runtime.h>
#include <cstdint>

#define BATCH 2
#define NSEQ 2048
#define DMODEL 1024
#define NHEAD 16
#define DHEAD 64
#define ATT_SCALE 0.125f   // 1/sqrt(64)
#define NEG_BIG (-1e30f)

// TF32 GEMM tiling
#define PADM 136                       // 128 + 8: (8*tig + g) distinct mod 32 -> conflict-free
#define KSTEP 16
#define SBUF (KSTEP * PADM)            // uint2 per k-tile buffer   = 2176
#define SMAT (2 * SBUF)                // per matrix, double-buffered = 4352
#define GEMM_SMEM_BYTES (2 * SMAT * (int)sizeof(uint2))   // 69632

// Attention smem: qs f32[128][68] | ks u2[64][68] | vs u2[64][68] | ps f32[128][68]
#define ATT_QS_BYTES   34816
#define ATT_KS_OFF     34816
#define ATT_VS_OFF     69632
#define ATT_PS_OFF     104448
#define ATT_SMEM_BYTES 139264

// Scratch (allocation-free: __device__ globals)
__device__ float g_q[(size_t)BATCH * NHEAD * NSEQ * DHEAD];   // [b,h,n,dh]
__device__ float g_k[(size_t)BATCH * NHEAD * NSEQ * DHEAD];
__device__ float g_v[(size_t)BATCH * NHEAD * NSEQ * DHEAD];
__device__ float g_y[(size_t)BATCH * NSEQ * DMODEL];          // [b,n,d]

// ---------------------------------------------------------------------------
// TF32 helpers
// ---------------------------------------------------------------------------
__device__ __forceinline__ unsigned f2tf(float x) {
    unsigned r;
    asm("cvt.rna.tf32.f32 %0, %1;" : "=r"(r) : "f"(x));
    return r;
}
// split x into (hi, lo) tf32 pair: x ~= hi + lo, |residual| ~ 2^-21 |x|
__device__ __forceinline__ uint2 split_tf32(float x) {
    unsigned hi = f2tf(x);
    float lof = x - __uint_as_float(hi);
    return make_uint2(hi, f2tf(lof));
}
__device__ __forceinline__ void mma8(float d[4], const unsigned a[4],
                                     unsigned b0, unsigned b1) {
    asm volatile(
        "mma.sync.aligned.m16n8k8.row.col.f32.tf32.tf32.f32 "
        "{%0,%1,%2,%3}, {%4,%5,%6,%7}, {%8,%9}, {%0,%1,%2,%3};"
        : "+f"(d[0]), "+f"(d[1]), "+f"(d[2]), "+f"(d[3])
        : "r"(a[0]), "r"(a[1]), "r"(a[2]), "r"(a[3]), "r"(b0), "r"(b1));
}

// ===========================================================================
// 3xTF32 NT sgemm core: C[m][c] = sum_k A[m][k] * B[c][k], K = DMODEL.
// 128x128 block, 256 threads (8 warps, 2x4 warp grid, 64x32 warp tile),
// k-step 16, double-buffered smem of (hi,lo) uint2 pairs.
// Fragment map (m16n8k8): a0=(g,tig) a1=(g+8,tig) a2=(g,tig+4) a3=(g+8,tig+4)
//                         b0=(k=tig,n=g) b1=(k=tig+4,n=g)
//                         c0=(g,2tig) c1=(g,2tig+1) c2,c3 = rows +8
// ===========================================================================
#define GEMM_TC_BODY(APTR, BPTR)                                               \
    extern __shared__ uint2 su[];                                              \
    uint2* As = su;                                                            \
    uint2* Bs = su + SMAT;                                                     \
    const int tid = threadIdx.x;                                               \
    const int lane = tid & 31, wid = tid >> 5;                                 \
    const int g = lane >> 2, tig = lane & 3;                                   \
    const int warpM = wid >> 2, warpN = wid & 3;                               \
    const int mBase = blockIdx.y << 7, cBase = blockIdx.x << 7;                \
    const int lrow = tid >> 1, lkc = (tid & 1) << 3;                           \
    const float* aptr = (APTR) + (size_t)(mBase + lrow) * DMODEL + lkc;        \
    const float* bptr = (BPTR) + (size_t)(cBase + lrow) * DMODEL + lkc;        \
    float acc[4][4][4] = {};                                                   \
    {   /* preload tile 0 into buffer 0 */                                     \
        float4 av0 = *(const float4*)(aptr);                                   \
        float4 av1 = *(const float4*)(aptr + 4);                               \
        float4 bv0 = *(const float4*)(bptr);                                   \
        float4 bv1 = *(const float4*)(bptr + 4);                               \
        float a8[8] = {av0.x, av0.y, av0.z, av0.w, av1.x, av1.y, av1.z, av1.w};\
        float b8[8] = {bv0.x, bv0.y, bv0.z, bv0.w, bv1.x, bv1.y, bv1.z, bv1.w};\
        _Pragma("unroll")                                                      \
        for (int j = 0; j < 8; j++) {                                          \
            As[(lkc + j) * PADM + lrow] = split_tf32(a8[j]);                   \
            Bs[(lkc + j) * PADM + lrow] = split_tf32(b8[j]);                   \
        }                                                                      \
    }                                                                          \
    __syncthreads();                                                           \
    int buf = 0;                                                               \
    for (int kt = 0; kt < DMODEL / KSTEP; kt++) {                              \
        float a8[8], b8[8];                                                    \
        const bool more = (kt + 1) < DMODEL / KSTEP;                           \
        if (more) {                                                            \
            const int off = (kt + 1) * KSTEP;                                  \
            float4 av0 = *(const float4*)(aptr + off);                         \
            float4 av1 = *(const float4*)(aptr + off + 4);                     \
            float4 bv0 = *(const float4*)(bptr + off);                         \
            float4 bv1 = *(const float4*)(bptr + off + 4);                     \
            a8[0]=av0.x; a8[1]=av0.y; a8[2]=av0.z; a8[3]=av0.w;                \
            a8[4]=av1.x; a8[5]=av1.y; a8[6]=av1.z; a8[7]=av1.w;                \
            b8[0]=bv0.x; b8[1]=bv0.y; b8[2]=bv0.z; b8[3]=bv0.w;                \
            b8[4]=bv1.x; b8[5]=bv1.y; b8[6]=bv1.z; b8[7]=bv1.w;                \
        }                                                                      \
        const int bofs = buf * SBUF;                                           \
        _Pragma("unroll")                                                      \
        for (int kc = 0; kc < KSTEP; kc += 8) {                                \
            unsigned ahi[4][4], alo[4][4], bhi[4][2], blo[4][2];               \
            const int kA = kc + tig;                                           \
            _Pragma("unroll")                                                  \
            for (int mf = 0; mf < 4; mf++) {                                   \
                const int r = (warpM << 6) + (mf << 4) + g;                    \
                uint2 p0 = As[bofs + kA * PADM + r];                           \
                uint2 p1 = As[bofs + kA * PADM + r + 8];                       \
                uint2 p2 = As[bofs + (kA + 4) * PADM + r];                     \
                uint2 p3 = As[bofs + (kA + 4) * PADM + r + 8];                 \
                ahi[mf][0] = p0.x; alo[mf][0] = p0.y;                          \
                ahi[mf][1] = p1.x; alo[mf][1] = p1.y;                          \
                ahi[mf][2] = p2.x; alo[mf][2] = p2.y;                          \
                ahi[mf][3] = p3.x; alo[mf][3] = p3.y;                          \
            }                                                                  \
            _Pragma("unroll")                                                  \
            for (int nf = 0; nf < 4; nf++) {                                   \
                const int n = (warpN << 5) + (nf << 3) + g;                    \
                uint2 q0 = Bs[bofs + kA * PADM + n];                           \
                uint2 q1 = Bs[bofs + (kA + 4) * PADM + n];                     \
                bhi[nf][0] = q0.x; blo[nf][0] = q0.y;                          \
                bhi[nf][1] = q1.x; blo[nf][1] = q1.y;                          \
            }                                                                  \
            _Pragma("unroll")                                                  \
            for (int mf = 0; mf < 4; mf++) {                                   \
                _Pragma("unroll")                                              \
                for (int nf = 0; nf < 4; nf++) {                               \
                    mma8(acc[mf][nf], ahi[mf], bhi[nf][0], bhi[nf][1]);        \
                    mma8(acc[mf][nf], alo[mf], bhi[nf][0], bhi[nf][1]);        \
                    mma8(acc[mf][nf], ahi[mf], blo[nf][0], blo[nf][1]);        \
                }                                                              \
            }                                                                  \
        }                                                                      \
        if (more) {                                                            \
            const int nofs = (buf ^ 1) * SBUF;                                 \
            _Pragma("unroll")                                                  \
            for (int j = 0; j < 8; j++) {                                      \
                As[nofs + (lkc + j) * PADM + lrow] = split_tf32(a8[j]);        \
                Bs[nofs + (lkc + j) * PADM + lrow] = split_tf32(b8[j]);        \
            }                                                                  \
            __syncthreads();                                                   \
            buf ^= 1;                                                          \
        }                                                                      \
    }

// ---------------------------------------------------------------------------
// Kernel 1: qkv = x @ Wqkv^T, scattered into g_q/g_k/g_v in [b,h,n,dh] layout.
// grid (3072/128, 4096/128) = (24, 32)
// ---------------------------------------------------------------------------
__global__ __launch_bounds__(256, 2) void qkv_kernel(const float* __restrict__ x,
                                                     const float* __restrict__ W) {
    GEMM_TC_BODY(x, W)

#pragma unroll
    for (int mf = 0; mf < 4; mf++) {
#pragma unroll
        for (int nf = 0; nf < 4; nf++) {
            const int c = cBase + (warpN << 5) + (nf << 3) + (tig << 1);
            const int three = c >> 10;
            const int hh = (c >> 6) & (NHEAD - 1);
            const int dh0 = c & 63;
            float* dst = (three == 0) ? g_q : (three == 1) ? g_k : g_v;
            const int m0 = mBase + (warpM << 6) + (mf << 4) + g;
#pragma unroll
            for (int rr = 0; rr < 2; rr++) {
                const int m = m0 + rr * 8;
                const int b = m >> 11;
                const int n = m & (NSEQ - 1);
                const size_t idx = (((size_t)(b * NHEAD + hh) * NSEQ + n) << 6) + dh0;
                *(float2*)&dst[idx] =
                    make_float2(acc[mf][nf][rr * 2], acc[mf][nf][rr * 2 + 1]);
            }
        }
    }
}

// ---------------------------------------------------------------------------
// Kernel 3: out = y @ Wproj^T + bproj.   grid (1024/128, 4096/128) = (8, 32)
// ---------------------------------------------------------------------------
__global__ __launch_bounds__(256, 2) void proj_kernel(const float* __restrict__ Wp,
                                                      const float* __restrict__ bproj,
                                                      float* __restrict__ out) {
    GEMM_TC_BODY(g_y, Wp)

#pragma unroll
    for (int mf = 0; mf < 4; mf++) {
#pragma unroll
        for (int nf = 0; nf < 4; nf++) {
            const int c = cBase + (warpN << 5) + (nf << 3) + (tig << 1);
            const float2 bb = *(const float2*)&bproj[c];
            const int m0 = mBase + (warpM << 6) + (mf << 4) + g;
#pragma unroll
            for (int rr = 0; rr < 2; rr++) {
                const int m = m0 + rr * 8;
                *(float2*)&out[(size_t)m * DMODEL + c] =
                    make_float2(acc[mf][nf][rr * 2] + bb.x,
                                acc[mf][nf][rr * 2 + 1] + bb.y);
            }
        }
    }
}

// ---------------------------------------------------------------------------
// Kernel 2: flash attention on tensor pipe (3xTF32 mma for QK^T and PV).
// grid (2048/128 = 16, 32). 256 threads = 8 warps; warp w owns q-rows
// [16w, 16w+16). Per 64-key tile: S(16x64) via m16n8k8 (K from smem
// pre-split uint2, dh-major), softmax in c-frag registers (quad shfl),
// P -> warp-private smem (fp32) -> reload as A-frags (split at load),
// O(16x64) += P V (V pre-split uint2, j-major). Prefix-mask early exit.
// ---------------------------------------------------------------------------
__global__ __launch_bounds__(256) void attn_kernel(const float* __restrict__ attn_bias,
                                                   const unsigned int* __restrict__ mask) {
    extern __shared__ __align__(16) char smraw[];
    float* qs = (float*)smraw;                       // [128][68] fp32
    uint2* ks = (uint2*)(smraw + ATT_KS_OFF);        // [64 dh][68 j] (hi,lo)
    uint2* vs = (uint2*)(smraw + ATT_VS_OFF);        // [64 j][68 dh] (hi,lo)
    float* ps = (float*)(smraw + ATT_PS_OFF);        // [128][68] fp32

    const int tid = threadIdx.x;
    const int lane = tid & 31, wid = tid >> 5;
    const int g = lane >> 2, tig = lane & 3;
    const int q0 = blockIdx.x << 7;
    const int bh = blockIdx.y;
    const int b = bh >> 4, h = bh & 15;

    const float* qg = g_q + (size_t)bh * NSEQ * DHEAD;
    const float* kg = g_k + (size_t)bh * NSEQ * DHEAD;
    const float* vg = g_v + (size_t)bh * NSEQ * DHEAD;
    const float* biasg = attn_bias + ((size_t)b * NSEQ + q0) * NSEQ;
    const unsigned int* maskg = mask + b * NSEQ;

    // Load Q tile (128x64): 8192 floats / 256 threads = 8 float4 each
#pragma unroll
    for (int t = 0; t < 8; t++) {
        int p = tid + (t << 8);
        int r = p >> 4, c = (p & 15) << 2;
        *(float4*)&qs[r * 68 + c] = *(const float4*)&qg[(size_t)(q0 + r) * 64 + c];
    }

    float o[8][4] = {};
    float m_a = NEG_BIG, m_b = NEG_BIG, l_a = 0.f, l_b = 0.f;
    const int rA = (wid << 4) + g;       // warp row (lane rows g / g+8)
    const int rB = rA + 8;

    const int jrow = tid >> 2;           // K/V fill: key row 0..63
    const int dc = (tid & 3) << 2;       // dh base 0,4,8,12

    for (int kt = 0; kt < NSEQ / 64; kt++) {
        const int kb = kt << 6;
        if (maskg[kb] == 0u) break;      // prefix mask: all later tiles masked

        // ---- fill K (transposed, split) and V (split) ----
        float4 kvv[4], vvv[4];
#pragma unroll
        for (int u = 0; u < 4; u++) {
            kvv[u] = *(const float4*)&kg[(size_t)(kb + jrow) * 64 + dc + u * 16];
            vvv[u] = *(const float4*)&vg[(size_t)(kb + jrow) * 64 + dc + u * 16];
        }
        __syncthreads();                 // prior tile's reads of ks/vs done
#pragma unroll
        for (int u = 0; u < 4; u++) {
            const int dh = dc + u * 16;
            ks[(dh + 0) * 68 + jrow] = split_tf32(kvv[u].x);
            ks[(dh + 1) * 68 + jrow] = split_tf32(kvv[u].y);
            ks[(dh + 2) * 68 + jrow] = split_tf32(kvv[u].z);
            ks[(dh + 3) * 68 + jrow] = split_tf32(kvv[u].w);
            vs[jrow * 68 + dh + 0] = split_tf32(vvv[u].x);
            vs[jrow * 68 + dh + 1] = split_tf32(vvv[u].y);
            vs[jrow * 68 + dh + 2] = split_tf32(vvv[u].z);
            vs[jrow * 68 + dh + 3] = split_tf32(vvv[u].w);
        }
        __syncthreads();

        // ---- S = Q K^T (3xTF32) ----
        float s[8][4] = {};
#pragma unroll
        for (int kc = 0; kc < 64; kc += 8) {
            const int kA = kc + tig;
            const uint2 a0 = split_tf32(qs[rA * 68 + kA]);
            const uint2 a1 = split_tf32(qs[rB * 68 + kA]);
            const uint2 a2 = split_tf32(qs[rA * 68 + kA + 4]);
            const uint2 a3 = split_tf32(qs[rB * 68 + kA + 4]);
            const unsigned ahi[4] = {a0.x, a1.x, a2.x, a3.x};
            const unsigned alo[4] = {a0.y, a1.y, a2.y, a3.y};
#pragma unroll
            for (int nt = 0; nt < 8; nt++) {
                const uint2 b0 = ks[kA * 68 + (nt << 3) + g];
                const uint2 b1 = ks[(kA + 4) * 68 + (nt << 3) + g];
                mma8(s[nt], ahi, b0.x, b1.x);
                mma8(s[nt], alo, b0.x, b1.x);
                mma8(s[nt], ahi, b0.y, b1.y);
            }
        }

        // ---- scale + bias + mask, online softmax in c-frag layout ----
        float mxa = NEG_BIG, mxb = NEG_BIG;
#pragma unroll
        for (int nt = 0; nt < 8; nt++) {
            const int col = kb + (nt << 3) + (tig << 1);
            const uint2 mk = *(const uint2*)&maskg[col];
            const float2 ba = *(const float2*)&biasg[(size_t)rA * NSEQ + col];
            const float2 bc = *(const float2*)&biasg[(size_t)rB * NSEQ + col];
            s[nt][0] = mk.x ? fmaf(s[nt][0], ATT_SCALE, ba.x) : NEG_BIG;
            s[nt][1] = mk.y ? fmaf(s[nt][1], ATT_SCALE, ba.y) : NEG_BIG;
            s[nt][2] = mk.x ? fmaf(s[nt][2], ATT_SCALE, bc.x) : NEG_BIG;
            s[nt][3] = mk.y ? fmaf(s[nt][3], ATT_SCALE, bc.y) : NEG_BIG;
            mxa = fmaxf(mxa, fmaxf(s[nt][0], s[nt][1]));
            mxb = fmaxf(mxb, fmaxf(s[nt][2], s[nt][3]));
        }
        mxa = fmaxf(mxa, __shfl_xor_sync(0xffffffffu, mxa, 1));
        mxa = fmaxf(mxa, __shfl_xor_sync(0xffffffffu, mxa, 2));
        mxb = fmaxf(mxb, __shfl_xor_sync(0xffffffffu, mxb, 1));
        mxb = fmaxf(mxb, __shfl_xor_sync(0xffffffffu, mxb, 2));
        const float mna = fmaxf(m_a, mxa), mnb = fmaxf(m_b, mxb);
        const float ala = __expf(m_a - mna), alb = __expf(m_b - mnb);
        float rsa = 0.f, rsb = 0.f;
#pragma unroll
        for (int nt = 0; nt < 8; nt++) {
            const float p0 = __expf(s[nt][0] - mna);
            const float p1 = __expf(s[nt][1] - mna);
            const float p2 = __expf(s[nt][2] - mnb);
            const float p3 = __expf(s[nt][3] - mnb);
            rsa += p0 + p1; rsb += p2 + p3;
            const int jc = (nt << 3) + (tig << 1);
            *(float2*)&ps[rA * 68 + jc] = make_float2(p0, p1);
            *(float2*)&ps[rB * 68 + jc] = make_float2(p2, p3);
            o[nt][0] *= ala; o[nt][1] *= ala;
            o[nt][2] *= alb; o[nt][3] *= alb;
        }
        rsa += __shfl_xor_sync(0xffffffffu, rsa, 1);
        rsa += __shfl_xor_sync(0xffffffffu, rsa, 2);
        rsb += __shfl_xor_sync(0xffffffffu, rsb, 1);
        rsb += __shfl_xor_sync(0xffffffffu, rsb, 2);
        l_a = l_a * ala + rsa;  l_b = l_b * alb + rsb;
        m_a = mna;  m_b = mnb;
        __syncwarp();                    // ps: c-frag writes -> a-frag reads

        // ---- O += P V (3xTF32) ----
#pragma unroll
        for (int kc = 0; kc < 64; kc += 8) {
            const int kA = kc + tig;
            const uint2 a0 = split_tf32(ps[rA * 68 + kA]);
            const uint2 a1 = split_tf32(ps[rB * 68 + kA]);
            const uint2 a2 = split_tf32(ps[rA * 68 + kA + 4]);
            const uint2 a3 = split_tf32(ps[rB * 68 + kA + 4]);
            const unsigned phi[4] = {a0.x, a1.x, a2.x, a3.x};
            const unsigned plo[4] = {a0.y, a1.y, a2.y, a3.y};
#pragma unroll
            for (int nt = 0; nt < 8; nt++) {
                const uint2 b0 = vs[kA * 68 + (nt << 3) + g];
                const uint2 b1 = vs[(kA + 4) * 68 + (nt << 3) + g];
                mma8(o[nt], phi, b0.x, b1.x);
                mma8(o[nt], plo, b0.x, b1.x);
                mma8(o[nt], phi, b0.y, b1.y);
            }
        }
    }

    // ---- epilogue: normalize, write y[b, n, h*64 + dh] ----
    const float iva = 1.0f / l_a, ivb = 1.0f / l_b;
#pragma unroll
    for (int nt = 0; nt < 8; nt++) {
        const int col = (h << 6) + (nt << 3) + (tig << 1);
        *(float2*)&g_y[((size_t)(b * NSEQ) + q0 + rA) * DMODEL + col] =
            make_float2(o[nt][0] * iva, o[nt][1] * iva);
        *(float2*)&g_y[((size_t)(b * NSEQ) + q0 + rB) * DMODEL + col] =
            make_float2(o[nt][2] * ivb, o[nt][3] * ivb);
    }
}

// ---------------------------------------------------------------------------
extern "C" void kernel_launch(void* const* d_in, const int* in_sizes, int n_in,
                              void* d_out, int out_size) {
    const float* x          = (const float*)d_in[0];
    const float* attn_bias  = (const float*)d_in[1];
    const unsigned int* msk = (const unsigned int*)d_in[2];
    const float* Wqkv       = (const float*)d_in[3];
    const float* Wproj      = (const float*)d_in[4];
    const float* bproj      = (const float*)d_in[5];
    float* out = (float*)d_out;

    (void)in_sizes; (void)n_in; (void)out_size;

    cudaFuncSetAttribute((const void*)qkv_kernel,
                         cudaFuncAttributeMaxDynamicSharedMemorySize, GEMM_SMEM_BYTES);
    cudaFuncSetAttribute((const void*)proj_kernel,
                         cudaFuncAttributeMaxDynamicSharedMemorySize, GEMM_SMEM_BYTES);
    cudaFuncSetAttribute((const void*)attn_kernel,
                         cudaFuncAttributeMaxDynamicSharedMemorySize, ATT_SMEM_BYTES);

    qkv_kernel<<<dim3(24, 32), 256, GEMM_SMEM_BYTES>>>(x, Wqkv);
    attn_kernel<<<dim3(NSEQ / 128, BATCH * NHEAD), 256, ATT_SMEM_BYTES>>>(attn_bias, msk);
    proj_kernel<<<dim3(8, 32), 256, GEMM_SMEM_BYTES>>>(Wproj, bproj, out);
}